// round 16
// baseline (speedup 1.0000x reference)
#include <cuda_runtime.h>
#include <cuda_fp16.h>
#include <math.h>

#define Nn 8192
#define Dd 512
#define SEGCAP 192   // per-1024-segment candidate cap (exact fallback if hit)
#define RPB 4        // rows per block in lse pass

// ---------------- static device scratch (symbol-access only) ----------------
static __device__ float  d_K  [(size_t)Nn * Nn];   // log_K fp32 (exact grid)
static __device__ float  d_KT [(size_t)Nn * Nn];   // transpose (same bits)
static __device__ __half d_Kh [(size_t)Nn * Nn];   // fp16 screening copy
static __device__ __half d_KTh[(size_t)Nn * Nn];   // fp16 screening copy (T)
static __device__ float d_alpha[Nn];
static __device__ float d_beta [Nn];
static __device__ float d_xsq[Nn];
static __device__ float d_ysq[Nn];
static __device__ int   d_idx[Nn];

// ---- FROZEN NUMERICS (Round 8 pass): XLA-CPU cephes exp, FMA-contracted ----
static __device__ __forceinline__ float exp_fma(float x) {
    x = fminf(x, 88.3762626647950f);
    x = fmaxf(x, -88.3762626647949f);
    float fx = floorf(__fmaf_rn(x, 1.44269504088896341f, 0.5f));
    float r  = __fmaf_rn(fx, -0.693359375f, x);
    r        = __fmaf_rn(fx,  2.12194440e-4f, r);
    float z  = __fmul_rn(r, r);
    float y  = __fmaf_rn(1.9875691500e-4f, r, 1.3981999507e-3f);
    y = __fmaf_rn(y, r, 8.3334519073e-3f);
    y = __fmaf_rn(y, r, 4.1665795894e-2f);
    y = __fmaf_rn(y, r, 1.6666665459e-1f);
    y = __fmaf_rn(y, r, 5.0000001201e-1f);
    y = __fmaf_rn(y, z, r);
    y = __fadd_rn(1.0f, y);
    int n = (int)fx;
    float s = __int_as_float((unsigned)(n + 127) << 23);
    return __fmul_rn(y, s);
}

// ---- FROZEN: XLA-CPU cephes log, FMA-contracted (S >= 1 here) ----
static __device__ __forceinline__ float log_fma(float x) {
    int bits = __float_as_int(x);
    int e = (bits >> 23) - 126;
    float mant = __int_as_float((bits & 0x007fffff) | 0x3f000000);  // [0.5,1)
    if (mant < 0.707106781186547524f) {
        e -= 1;
        mant = __fadd_rn(__fadd_rn(mant, mant), -1.0f);
    } else {
        mant = __fadd_rn(mant, -1.0f);
    }
    float z = __fmul_rn(mant, mant);
    float y = 7.0376836292e-2f;
    y = __fmaf_rn(y, mant, -1.1514610310e-1f);
    y = __fmaf_rn(y, mant,  1.1676998740e-1f);
    y = __fmaf_rn(y, mant, -1.2420140846e-1f);
    y = __fmaf_rn(y, mant,  1.4249322787e-1f);
    y = __fmaf_rn(y, mant, -1.6668057665e-1f);
    y = __fmaf_rn(y, mant,  2.0000714765e-1f);
    y = __fmaf_rn(y, mant, -2.4999993993e-1f);
    y = __fmaf_rn(y, mant,  3.3333331174e-1f);
    y = __fmul_rn(__fmul_rn(y, mant), z);
    float fe = (float)e;
    y = __fmaf_rn(fe, -2.12194440e-4f, y);
    y = __fmaf_rn(-0.5f, z, y);
    float res = __fadd_rn(mant, y);
    res = __fmaf_rn(fe, 0.693359375f, res);
    return res;
}

// ---------------- init ----------------
__global__ void init_kernel() {
    int i = blockIdx.x * blockDim.x + threadIdx.x;
    if (i < Nn) { d_beta[i] = 0.0f; d_alpha[i] = 0.0f; }
}

// ---------------- row squared norms: 8-slot FMA chains (FROZEN) -------------
__global__ void rowsq_kernel(const float* __restrict__ X0,
                             const float* __restrict__ X1) {
    int half = (gridDim.x * blockDim.x) >> 1;
    int g = blockIdx.x * blockDim.x + threadIdx.x;
    bool second = g >= half;
    int row = second ? (g - half) : g;
    const float* x = (second ? X1 : X0) + (size_t)row * Dd;
    float s[8];
#pragma unroll
    for (int i = 0; i < 8; i++) s[i] = 0.0f;
    for (int k = 0; k < Dd; k += 8) {
#pragma unroll
        for (int i = 0; i < 8; i++) {
            float v = x[k + i];
            s[i] = __fmaf_rn(v, v, s[i]);
        }
    }
    float w0 = __fadd_rn(s[0], s[4]);
    float w1 = __fadd_rn(s[1], s[5]);
    float w2 = __fadd_rn(s[2], s[6]);
    float w3 = __fadd_rn(s[3], s[7]);
    float r = __fadd_rn(__fadd_rn(w0, w2), __fadd_rn(w1, w3));
    if (second) d_ysq[row] = r; else d_xsq[row] = r;
}

// ------- GEMM -> K fp32 + fp16 copy. Double-buffered smem, K-tile 16. -------
// FROZEN numerics: each acc[i][j] is ONE ascending-k FMA chain.
__global__ void __launch_bounds__(256) gemm_kernel(const float* __restrict__ A,
                                                   const float* __restrict__ B) {
    __shared__ float As[2][16][128];
    __shared__ float Bs[2][16][128];
    int bi = blockIdx.y << 7, bj = blockIdx.x << 7;
    int t  = threadIdx.x;
    int tx = t & 15, ty = t >> 4;
    int lrow = t & 127;
    int kh   = (t >> 7) << 3;   // 0 or 8

    float acc[8][8];
#pragma unroll
    for (int i = 0; i < 8; i++)
#pragma unroll
        for (int j = 0; j < 8; j++) acc[i][j] = 0.f;

    const float* Ag = A + (size_t)(bi + lrow) * Dd + kh;
    const float* Bg = B + (size_t)(bj + lrow) * Dd + kh;

    float4 pa0 = *(const float4*)(Ag);
    float4 pa1 = *(const float4*)(Ag + 4);
    float4 pb0 = *(const float4*)(Bg);
    float4 pb1 = *(const float4*)(Bg + 4);

    As[0][kh + 0][lrow] = pa0.x; As[0][kh + 1][lrow] = pa0.y;
    As[0][kh + 2][lrow] = pa0.z; As[0][kh + 3][lrow] = pa0.w;
    As[0][kh + 4][lrow] = pa1.x; As[0][kh + 5][lrow] = pa1.y;
    As[0][kh + 6][lrow] = pa1.z; As[0][kh + 7][lrow] = pa1.w;
    Bs[0][kh + 0][lrow] = pb0.x; Bs[0][kh + 1][lrow] = pb0.y;
    Bs[0][kh + 2][lrow] = pb0.z; Bs[0][kh + 3][lrow] = pb0.w;
    Bs[0][kh + 4][lrow] = pb1.x; Bs[0][kh + 5][lrow] = pb1.y;
    Bs[0][kh + 6][lrow] = pb1.z; Bs[0][kh + 7][lrow] = pb1.w;
    __syncthreads();

    int buf = 0;
    for (int kt = 0; kt < Dd; kt += 16) {
        bool last = (kt + 16 >= Dd);
        if (!last) {
            pa0 = *(const float4*)(Ag + kt + 16);
            pa1 = *(const float4*)(Ag + kt + 20);
            pb0 = *(const float4*)(Bg + kt + 16);
            pb1 = *(const float4*)(Bg + kt + 20);
        }
#pragma unroll
        for (int k = 0; k < 16; k++) {          // ascending k — FROZEN chain
            float a[8], b[8];
            *(float4*)&a[0] = *(const float4*)&As[buf][k][(ty << 3)];
            *(float4*)&a[4] = *(const float4*)&As[buf][k][(ty << 3) + 4];
            *(float4*)&b[0] = *(const float4*)&Bs[buf][k][(tx << 3)];
            *(float4*)&b[4] = *(const float4*)&Bs[buf][k][(tx << 3) + 4];
#pragma unroll
            for (int i = 0; i < 8; i++)
#pragma unroll
                for (int j = 0; j < 8; j++)
                    acc[i][j] = __fmaf_rn(a[i], b[j], acc[i][j]);
        }
        if (!last) {
            int nb = buf ^ 1;
            As[nb][kh + 0][lrow] = pa0.x; As[nb][kh + 1][lrow] = pa0.y;
            As[nb][kh + 2][lrow] = pa0.z; As[nb][kh + 3][lrow] = pa0.w;
            As[nb][kh + 4][lrow] = pa1.x; As[nb][kh + 5][lrow] = pa1.y;
            As[nb][kh + 6][lrow] = pa1.z; As[nb][kh + 7][lrow] = pa1.w;
            Bs[nb][kh + 0][lrow] = pb0.x; Bs[nb][kh + 1][lrow] = pb0.y;
            Bs[nb][kh + 2][lrow] = pb0.z; Bs[nb][kh + 3][lrow] = pb0.w;
            Bs[nb][kh + 4][lrow] = pb1.x; Bs[nb][kh + 5][lrow] = pb1.y;
            Bs[nb][kh + 6][lrow] = pb1.z; Bs[nb][kh + 7][lrow] = pb1.w;
        }
        __syncthreads();
        buf ^= 1;
    }

    int row0 = bi + (ty << 3);
    int col0 = bj + (tx << 3);
    float xs[8], ys[8];
#pragma unroll
    for (int i = 0; i < 8; i++) xs[i] = d_xsq[row0 + i];
#pragma unroll
    for (int j = 0; j < 8; j++) ys[j] = d_ysq[col0 + j];
#pragma unroll
    for (int i = 0; i < 8; i++) {
        float o[8];
        __half hh[8];
#pragma unroll
        for (int j = 0; j < 8; j++) {
            float nrm  = __fadd_rn(xs[i], ys[j]);
            float cost = __fmaf_rn(-2.0f, acc[i][j], nrm);
            o[j] = __fdiv_rn(-cost, 0.1f);
            hh[j] = __float2half(o[j]);
        }
        *(float4*)&d_K[(size_t)(row0 + i) * Nn + col0]     = *(float4*)&o[0];
        *(float4*)&d_K[(size_t)(row0 + i) * Nn + col0 + 4] = *(float4*)&o[4];
        *(uint4*)&d_Kh[(size_t)(row0 + i) * Nn + col0]     = *(uint4*)hh;
    }
}

// ---------------- transpose: K -> KT (fp32) + KTh (fp16), one-time ----------
__global__ void transpose_kernel() {
    __shared__ float tile[32][33];
    int tx = threadIdx.x, ty = threadIdx.y;
    int xi = (blockIdx.x << 5) + tx;
    int yi = (blockIdx.y << 5) + ty;
#pragma unroll
    for (int j = 0; j < 32; j += 8)
        tile[ty + j][tx] = d_K[(size_t)(yi + j) * Nn + xi];
    __syncthreads();
    int xo = (blockIdx.y << 5) + tx;
    int yo = (blockIdx.x << 5) + ty;
#pragma unroll
    for (int j = 0; j < 32; j += 8) {
        float v = tile[tx][ty + j];
        d_KT [(size_t)(yo + j) * Nn + xo] = v;
        d_KTh[(size_t)(yo + j) * Nn + xo] = __float2half(v);
    }
}

// ====== LSE PASS: 4 rows/block, register-direct fp16 screen =================
// Per row (identical FROZEN bit-path to R15): sweep1 max -> ballot collect at
// thr_s = m_s - 96 (fp16 superset proof) -> exact fp32 gather -> exact max ->
// parallel exp -> thread-per-row FROZEN-order additions (8-slot / sequential).
// vin (beta/alpha) reads are L1-hot across the block's 4 rows => L2 traffic /4.
template <int DIR>
__global__ void __launch_bounds__(256) lse_pass_kernel() {
    __shared__ float wmax[8];
    __shared__ float bmax_s[RPB];
    __shared__ float m_sh[RPB];
    __shared__ int   okr[RPB];
    __shared__ int   seg_cnt[RPB][8];
    __shared__ short seg_list[RPB][8][SEGCAP];
    __shared__ float seg_val[RPB][8][SEGCAP];

    int t   = threadIdx.x;
    int lane = t & 31, wid = t >> 5;
    int row0 = blockIdx.x * RPB;
    const __half* __restrict__ Hbase = (DIR == 0) ? d_Kh : d_KTh;
    const float*  __restrict__ Mbase = (DIR == 0) ? d_K  : d_KT;
    const float*  __restrict__ vin   = (DIR == 0) ? d_beta : d_alpha;

    int segbase = wid << 10;             // 1024 elems per warp segment

    for (int r = 0; r < RPB; r++) {
        const __half* Hs = Hbase + (size_t)(row0 + r) * Nn;
        const float*  Mx = Mbase + (size_t)(row0 + r) * Nn;

        // sweep 1: max only
        float lm = __int_as_float(0xff800000);
#pragma unroll
        for (int r2 = 0; r2 < 4; r2++) {
            int i0 = segbase + (r2 << 8) + (lane << 3);
            uint4 hv = *(const uint4*)(Hs + i0);
            __half2* hp = (__half2*)&hv;
            float4 b0 = *(const float4*)(vin + i0);
            float4 b1 = *(const float4*)(vin + i0 + 4);
            float2 f0 = __half22float2(hp[0]);
            float2 f1 = __half22float2(hp[1]);
            float2 f2 = __half22float2(hp[2]);
            float2 f3 = __half22float2(hp[3]);
            float z0 = __fadd_rn(f0.x, b0.x), z1 = __fadd_rn(f0.y, b0.y);
            float z2 = __fadd_rn(f1.x, b0.z), z3 = __fadd_rn(f1.y, b0.w);
            float z4 = __fadd_rn(f2.x, b1.x), z5 = __fadd_rn(f2.y, b1.y);
            float z6 = __fadd_rn(f3.x, b1.z), z7 = __fadd_rn(f3.y, b1.w);
            lm = fmaxf(lm, fmaxf(fmaxf(z0, z1), fmaxf(z2, z3)));
            lm = fmaxf(lm, fmaxf(fmaxf(z4, z5), fmaxf(z6, z7)));
        }
#pragma unroll
        for (int off = 16; off; off >>= 1)
            lm = fmaxf(lm, __shfl_down_sync(0xffffffffu, lm, off));
        if (lane == 0) { wmax[wid] = lm; seg_cnt[r][wid] = 0; }
        __syncthreads();
        if (t == 0) {
            float m = wmax[0];
#pragma unroll
            for (int w = 1; w < 8; w++) m = fmaxf(m, wmax[w]);
            bmax_s[r] = m;
        }
        __syncthreads();
        float thr_s = bmax_s[r] - 96.0f;

        // sweep 2 (L1-hot): mask + ascending emission
        int cnt = 0;
#pragma unroll
        for (int r2 = 0; r2 < 4; r2++) {
            int i0 = segbase + (r2 << 8) + (lane << 3);
            uint4 hv = *(const uint4*)(Hs + i0);
            __half2* hp = (__half2*)&hv;
            float4 b0 = *(const float4*)(vin + i0);
            float4 b1 = *(const float4*)(vin + i0 + 4);
            float2 f0 = __half22float2(hp[0]);
            float2 f1 = __half22float2(hp[1]);
            float2 f2 = __half22float2(hp[2]);
            float2 f3 = __half22float2(hp[3]);
            unsigned m8 = 0;
            m8 |= (__fadd_rn(f0.x, b0.x) >= thr_s) ? 1u   : 0u;
            m8 |= (__fadd_rn(f0.y, b0.y) >= thr_s) ? 2u   : 0u;
            m8 |= (__fadd_rn(f1.x, b0.z) >= thr_s) ? 4u   : 0u;
            m8 |= (__fadd_rn(f1.y, b0.w) >= thr_s) ? 8u   : 0u;
            m8 |= (__fadd_rn(f2.x, b1.x) >= thr_s) ? 16u  : 0u;
            m8 |= (__fadd_rn(f2.y, b1.y) >= thr_s) ? 32u  : 0u;
            m8 |= (__fadd_rn(f3.x, b1.z) >= thr_s) ? 64u  : 0u;
            m8 |= (__fadd_rn(f3.y, b1.w) >= thr_s) ? 128u : 0u;
            unsigned act = __ballot_sync(0xffffffffu, m8 != 0);
            while (act) {                      // act uniform across warp
                int la = __ffs(act) - 1;
                unsigned mm = __shfl_sync(0xffffffffu, m8, la);
                if (lane == 0) {
                    int base = (r2 << 8) + (la << 3);
                    while (mm) {
                        int b = __ffs(mm) - 1;
                        if (cnt < SEGCAP) seg_list[r][wid][cnt] = (short)(base + b);
                        cnt++;
                        mm &= mm - 1;
                    }
                }
                act &= act - 1;
            }
        }
        if (lane == 0) seg_cnt[r][wid] = cnt;
        __syncwarp();
        int cc = seg_cnt[r][wid]; if (cc > SEGCAP) cc = SEGCAP;
        for (int p = lane; p < cc; p += 32) {
            int idx = segbase + seg_list[r][wid][p];
            seg_val[r][wid][p] = __fadd_rn(Mx[idx], vin[idx]);
        }
        __syncthreads();
    }

    // per-row ok + exact max (threads 0..3, one row each)
    if (t < RPB) {
        bool ok = true;
#pragma unroll
        for (int w = 0; w < 8; w++) ok &= (seg_cnt[t][w] <= SEGCAP);
        okr[t] = ok;
        if (ok) {
            float m = __int_as_float(0xff800000);
            for (int w = 0; w < 8; w++) {
                int cnt = seg_cnt[t][w];
                for (int p = 0; p < cnt; p++) m = fmaxf(m, seg_val[t][w][p]);
            }
            m_sh[t] = m;
        }
    }
    __syncthreads();

    // parallel exp: warp pair (2r, 2r+1) handles row r, 4 segments each
    {
        int r = wid >> 1;
        if (okr[r]) {
            float m = m_sh[r];
            float thr = m - 70.0f;
            int s0 = (wid & 1) * 4;
#pragma unroll
            for (int s = 0; s < 4; s++) {
                int cnt = seg_cnt[r][s0 + s];
                for (int p = lane; p < cnt; p += 32) {
                    float zv = seg_val[r][s0 + s][p];
                    seg_val[r][s0 + s][p] = (zv >= thr) ? exp_fma(__fadd_rn(zv, -m)) : -1.0f;
                }
            }
        }
    }
    __syncthreads();

    // frozen-order additions, one thread per row
    if (t < RPB) {
        int row = row0 + t;
        if (okr[t]) {
            float m = m_sh[t];
            float S;
            if (DIR == 0) {
                float s[8];
#pragma unroll
                for (int i = 0; i < 8; i++) s[i] = 0.0f;
                for (int w = 0; w < 8; w++) {
                    int base = w << 10, cnt = seg_cnt[t][w];
                    for (int p = 0; p < cnt; p++) {
                        float e = seg_val[t][w][p];
                        if (e >= 0.0f) {
                            int idx = base + seg_list[t][w][p];
                            s[idx & 7] = __fadd_rn(s[idx & 7], e);
                        }
                    }
                }
                float w0 = __fadd_rn(s[0], s[4]);
                float w1 = __fadd_rn(s[1], s[5]);
                float w2 = __fadd_rn(s[2], s[6]);
                float w3 = __fadd_rn(s[3], s[7]);
                S = __fadd_rn(__fadd_rn(w0, w2), __fadd_rn(w1, w3));
            } else {
                float acc = 0.0f;
                for (int w = 0; w < 8; w++) {
                    int cnt = seg_cnt[t][w];
                    for (int p = 0; p < cnt; p++) {
                        float e = seg_val[t][w][p];
                        if (e >= 0.0f) acc = __fadd_rn(acc, e);
                    }
                }
                S = acc;
            }
            float res = -__fadd_rn(log_fma(S), m);
            if (DIR == 0) d_alpha[row] = res; else d_beta[row] = res;
        } else {
            // exact in-order fallback over full fp32 row (never expected)
            const float* Mx = Mbase + (size_t)row * Nn;
            float m = __int_as_float(0xff800000);
            for (int q = 0; q < Nn; q++)
                m = fmaxf(m, __fadd_rn(Mx[q], vin[q]));
            float thr = m - 70.0f;
            float S;
            if (DIR == 0) {
                float s[8];
#pragma unroll
                for (int i = 0; i < 8; i++) s[i] = 0.0f;
                for (int q = 0; q < Nn; q++) {
                    float zv = __fadd_rn(Mx[q], vin[q]);
                    if (zv >= thr)
                        s[q & 7] = __fadd_rn(s[q & 7], exp_fma(__fadd_rn(zv, -m)));
                }
                float w0 = __fadd_rn(s[0], s[4]);
                float w1 = __fadd_rn(s[1], s[5]);
                float w2 = __fadd_rn(s[2], s[6]);
                float w3 = __fadd_rn(s[3], s[7]);
                S = __fadd_rn(__fadd_rn(w0, w2), __fadd_rn(w1, w3));
            } else {
                float acc = 0.0f;
                for (int q = 0; q < Nn; q++) {
                    float zv = __fadd_rn(Mx[q], vin[q]);
                    if (zv >= thr)
                        acc = __fadd_rn(acc, exp_fma(__fadd_rn(zv, -m)));
                }
                S = acc;
            }
            float res = -__fadd_rn(log_fma(S), m);
            if (DIR == 0) d_alpha[row] = res; else d_beta[row] = res;
        }
    }
}

// ---------------- argmax over P = exp_fma(fl(fl(K+alpha)+beta)) (FROZEN) ----
__global__ void __launch_bounds__(256) argmax_kernel() {
    int rowbase = blockIdx.x << 3;
    int t = threadIdx.x;
    float a[8];
#pragma unroll
    for (int r = 0; r < 8; r++) a[r] = d_alpha[rowbase + r];

    float bv[8]; int bi_[8];
#pragma unroll
    for (int r = 0; r < 8; r++) { bv[r] = -1.0f; bi_[r] = Nn; }

    for (int c = t << 2; c < Nn; c += 1024) {
        float4 betav = *(const float4*)(d_beta + c);
#pragma unroll
        for (int r = 0; r < 8; r++) {
            float4 v = *(const float4*)(d_K + (size_t)(rowbase + r) * Nn + c);
            float w;
            w = exp_fma(__fadd_rn(__fadd_rn(v.x, a[r]), betav.x)); if (w > bv[r]) { bv[r] = w; bi_[r] = c; }
            w = exp_fma(__fadd_rn(__fadd_rn(v.y, a[r]), betav.y)); if (w > bv[r]) { bv[r] = w; bi_[r] = c + 1; }
            w = exp_fma(__fadd_rn(__fadd_rn(v.z, a[r]), betav.z)); if (w > bv[r]) { bv[r] = w; bi_[r] = c + 2; }
            w = exp_fma(__fadd_rn(__fadd_rn(v.w, a[r]), betav.w)); if (w > bv[r]) { bv[r] = w; bi_[r] = c + 3; }
        }
    }
#pragma unroll
    for (int r = 0; r < 8; r++) {
#pragma unroll
        for (int off = 16; off; off >>= 1) {
            float ov = __shfl_down_sync(0xffffffffu, bv[r], off);
            int   oi = __shfl_down_sync(0xffffffffu, bi_[r], off);
            if (ov > bv[r] || (ov == bv[r] && oi < bi_[r])) { bv[r] = ov; bi_[r] = oi; }
        }
    }
    __shared__ float svv[8][8];
    __shared__ int   sii[8][8];
    int wid = t >> 5, lane = t & 31;
    if (lane == 0) {
#pragma unroll
        for (int r = 0; r < 8; r++) { svv[r][wid] = bv[r]; sii[r][wid] = bi_[r]; }
    }
    __syncthreads();
    if (t < 8) {
        float V = -1.0f; int I = Nn;
#pragma unroll
        for (int w = 0; w < 8; w++) {
            float ov = svv[t][w]; int oi = sii[t][w];
            if (ov > V || (ov == V && oi < I)) { V = ov; I = oi; }
        }
        d_idx[rowbase + t] = I;
    }
}

// ---------------- out = concat(x0, x1[idx]) ----------------
__global__ void output_kernel(const float* __restrict__ x0,
                              const float* __restrict__ x1,
                              float* __restrict__ out) {
    int row = blockIdx.x;
    int t   = threadIdx.x;
    const float4* s0 = (const float4*)(x0 + (size_t)row * Dd);
    ((float4*)(out + (size_t)row * Dd))[t] = s0[t];
    int j = d_idx[row];
    const float4* s1 = (const float4*)(x1 + (size_t)j * Dd);
    ((float4*)(out + (size_t)Nn * Dd + (size_t)row * Dd))[t] = s1[t];
}

// ---------------- launch ----------------
extern "C" void kernel_launch(void* const* d_in, const int* in_sizes, int n_in,
                              void* d_out, int out_size) {
    const float* x0 = (const float*)d_in[0];
    const float* x1 = (const float*)d_in[1];
    float* out = (float*)d_out;

    init_kernel<<<8, 1024>>>();
    rowsq_kernel<<<2 * (Nn / 256), 256>>>(x0, x1);

    dim3 gg(Nn / 128, Nn / 128);
    gemm_kernel<<<gg, 256>>>(x0, x1);

    dim3 tg(Nn / 32, Nn / 32), tb(32, 8);
    transpose_kernel<<<tg, tb>>>();

    for (int it = 0; it < 100; it++) {
        lse_pass_kernel<0><<<Nn / RPB, 256>>>();
        lse_pass_kernel<1><<<Nn / RPB, 256>>>();
    }

    argmax_kernel<<<Nn / 8, 256>>>();
    output_kernel<<<Nn, 128>>>(x0, x1, out);
}

// round 17
// speedup vs baseline: 1.4896x; 1.4896x over previous
#include <cuda_runtime.h>
#include <cuda_fp16.h>
#include <math.h>

#define Nn 8192
#define Dd 512
#define SEGCAP 192   // per-1024-segment candidate cap (exact fallback if hit)
#define RPB 4        // rows per block in lse pass (interleaved)

// ---------------- static device scratch (symbol-access only) ----------------
static __device__ float  d_K  [(size_t)Nn * Nn];   // log_K fp32 (exact grid)
static __device__ float  d_KT [(size_t)Nn * Nn];   // transpose (same bits)
static __device__ __half d_Kh [(size_t)Nn * Nn];   // fp16 screening copy
static __device__ __half d_KTh[(size_t)Nn * Nn];   // fp16 screening copy (T)
static __device__ float d_alpha[Nn];
static __device__ float d_beta [Nn];
static __device__ float d_xsq[Nn];
static __device__ float d_ysq[Nn];
static __device__ int   d_idx[Nn];

// ---- FROZEN NUMERICS (Round 8 pass): XLA-CPU cephes exp, FMA-contracted ----
static __device__ __forceinline__ float exp_fma(float x) {
    x = fminf(x, 88.3762626647950f);
    x = fmaxf(x, -88.3762626647949f);
    float fx = floorf(__fmaf_rn(x, 1.44269504088896341f, 0.5f));
    float r  = __fmaf_rn(fx, -0.693359375f, x);
    r        = __fmaf_rn(fx,  2.12194440e-4f, r);
    float z  = __fmul_rn(r, r);
    float y  = __fmaf_rn(1.9875691500e-4f, r, 1.3981999507e-3f);
    y = __fmaf_rn(y, r, 8.3334519073e-3f);
    y = __fmaf_rn(y, r, 4.1665795894e-2f);
    y = __fmaf_rn(y, r, 1.6666665459e-1f);
    y = __fmaf_rn(y, r, 5.0000001201e-1f);
    y = __fmaf_rn(y, z, r);
    y = __fadd_rn(1.0f, y);
    int n = (int)fx;
    float s = __int_as_float((unsigned)(n + 127) << 23);
    return __fmul_rn(y, s);
}

// ---- FROZEN: XLA-CPU cephes log, FMA-contracted (S >= 1 here) ----
static __device__ __forceinline__ float log_fma(float x) {
    int bits = __float_as_int(x);
    int e = (bits >> 23) - 126;
    float mant = __int_as_float((bits & 0x007fffff) | 0x3f000000);  // [0.5,1)
    if (mant < 0.707106781186547524f) {
        e -= 1;
        mant = __fadd_rn(__fadd_rn(mant, mant), -1.0f);
    } else {
        mant = __fadd_rn(mant, -1.0f);
    }
    float z = __fmul_rn(mant, mant);
    float y = 7.0376836292e-2f;
    y = __fmaf_rn(y, mant, -1.1514610310e-1f);
    y = __fmaf_rn(y, mant,  1.1676998740e-1f);
    y = __fmaf_rn(y, mant, -1.2420140846e-1f);
    y = __fmaf_rn(y, mant,  1.4249322787e-1f);
    y = __fmaf_rn(y, mant, -1.6668057665e-1f);
    y = __fmaf_rn(y, mant,  2.0000714765e-1f);
    y = __fmaf_rn(y, mant, -2.4999993993e-1f);
    y = __fmaf_rn(y, mant,  3.3333331174e-1f);
    y = __fmul_rn(__fmul_rn(y, mant), z);
    float fe = (float)e;
    y = __fmaf_rn(fe, -2.12194440e-4f, y);
    y = __fmaf_rn(-0.5f, z, y);
    float res = __fadd_rn(mant, y);
    res = __fmaf_rn(fe, 0.693359375f, res);
    return res;
}

// ---------------- init ----------------
__global__ void init_kernel() {
    int i = blockIdx.x * blockDim.x + threadIdx.x;
    if (i < Nn) { d_beta[i] = 0.0f; d_alpha[i] = 0.0f; }
}

// ---------------- row squared norms: 8-slot FMA chains (FROZEN) -------------
__global__ void rowsq_kernel(const float* __restrict__ X0,
                             const float* __restrict__ X1) {
    int half = (gridDim.x * blockDim.x) >> 1;
    int g = blockIdx.x * blockDim.x + threadIdx.x;
    bool second = g >= half;
    int row = second ? (g - half) : g;
    const float* x = (second ? X1 : X0) + (size_t)row * Dd;
    float s[8];
#pragma unroll
    for (int i = 0; i < 8; i++) s[i] = 0.0f;
    for (int k = 0; k < Dd; k += 8) {
#pragma unroll
        for (int i = 0; i < 8; i++) {
            float v = x[k + i];
            s[i] = __fmaf_rn(v, v, s[i]);
        }
    }
    float w0 = __fadd_rn(s[0], s[4]);
    float w1 = __fadd_rn(s[1], s[5]);
    float w2 = __fadd_rn(s[2], s[6]);
    float w3 = __fadd_rn(s[3], s[7]);
    float r = __fadd_rn(__fadd_rn(w0, w2), __fadd_rn(w1, w3));
    if (second) d_ysq[row] = r; else d_xsq[row] = r;
}

// ------- GEMM -> K fp32 + fp16 copy. Double-buffered smem, K-tile 16. -------
__global__ void __launch_bounds__(256) gemm_kernel(const float* __restrict__ A,
                                                   const float* __restrict__ B) {
    __shared__ float As[2][16][128];
    __shared__ float Bs[2][16][128];
    int bi = blockIdx.y << 7, bj = blockIdx.x << 7;
    int t  = threadIdx.x;
    int tx = t & 15, ty = t >> 4;
    int lrow = t & 127;
    int kh   = (t >> 7) << 3;   // 0 or 8

    float acc[8][8];
#pragma unroll
    for (int i = 0; i < 8; i++)
#pragma unroll
        for (int j = 0; j < 8; j++) acc[i][j] = 0.f;

    const float* Ag = A + (size_t)(bi + lrow) * Dd + kh;
    const float* Bg = B + (size_t)(bj + lrow) * Dd + kh;

    float4 pa0 = *(const float4*)(Ag);
    float4 pa1 = *(const float4*)(Ag + 4);
    float4 pb0 = *(const float4*)(Bg);
    float4 pb1 = *(const float4*)(Bg + 4);

    As[0][kh + 0][lrow] = pa0.x; As[0][kh + 1][lrow] = pa0.y;
    As[0][kh + 2][lrow] = pa0.z; As[0][kh + 3][lrow] = pa0.w;
    As[0][kh + 4][lrow] = pa1.x; As[0][kh + 5][lrow] = pa1.y;
    As[0][kh + 6][lrow] = pa1.z; As[0][kh + 7][lrow] = pa1.w;
    Bs[0][kh + 0][lrow] = pb0.x; Bs[0][kh + 1][lrow] = pb0.y;
    Bs[0][kh + 2][lrow] = pb0.z; Bs[0][kh + 3][lrow] = pb0.w;
    Bs[0][kh + 4][lrow] = pb1.x; Bs[0][kh + 5][lrow] = pb1.y;
    Bs[0][kh + 6][lrow] = pb1.z; Bs[0][kh + 7][lrow] = pb1.w;
    __syncthreads();

    int buf = 0;
    for (int kt = 0; kt < Dd; kt += 16) {
        bool last = (kt + 16 >= Dd);
        if (!last) {
            pa0 = *(const float4*)(Ag + kt + 16);
            pa1 = *(const float4*)(Ag + kt + 20);
            pb0 = *(const float4*)(Bg + kt + 16);
            pb1 = *(const float4*)(Bg + kt + 20);
        }
#pragma unroll
        for (int k = 0; k < 16; k++) {          // ascending k — FROZEN chain
            float a[8], b[8];
            *(float4*)&a[0] = *(const float4*)&As[buf][k][(ty << 3)];
            *(float4*)&a[4] = *(const float4*)&As[buf][k][(ty << 3) + 4];
            *(float4*)&b[0] = *(const float4*)&Bs[buf][k][(tx << 3)];
            *(float4*)&b[4] = *(const float4*)&Bs[buf][k][(tx << 3) + 4];
#pragma unroll
            for (int i = 0; i < 8; i++)
#pragma unroll
                for (int j = 0; j < 8; j++)
                    acc[i][j] = __fmaf_rn(a[i], b[j], acc[i][j]);
        }
        if (!last) {
            int nb = buf ^ 1;
            As[nb][kh + 0][lrow] = pa0.x; As[nb][kh + 1][lrow] = pa0.y;
            As[nb][kh + 2][lrow] = pa0.z; As[nb][kh + 3][lrow] = pa0.w;
            As[nb][kh + 4][lrow] = pa1.x; As[nb][kh + 5][lrow] = pa1.y;
            As[nb][kh + 6][lrow] = pa1.z; As[nb][kh + 7][lrow] = pa1.w;
            Bs[nb][kh + 0][lrow] = pb0.x; Bs[nb][kh + 1][lrow] = pb0.y;
            Bs[nb][kh + 2][lrow] = pb0.z; Bs[nb][kh + 3][lrow] = pb0.w;
            Bs[nb][kh + 4][lrow] = pb1.x; Bs[nb][kh + 5][lrow] = pb1.y;
            Bs[nb][kh + 6][lrow] = pb1.z; Bs[nb][kh + 7][lrow] = pb1.w;
        }
        __syncthreads();
        buf ^= 1;
    }

    int row0 = bi + (ty << 3);
    int col0 = bj + (tx << 3);
    float xs[8], ys[8];
#pragma unroll
    for (int i = 0; i < 8; i++) xs[i] = d_xsq[row0 + i];
#pragma unroll
    for (int j = 0; j < 8; j++) ys[j] = d_ysq[col0 + j];
#pragma unroll
    for (int i = 0; i < 8; i++) {
        float o[8];
        __half hh[8];
#pragma unroll
        for (int j = 0; j < 8; j++) {
            float nrm  = __fadd_rn(xs[i], ys[j]);
            float cost = __fmaf_rn(-2.0f, acc[i][j], nrm);
            o[j] = __fdiv_rn(-cost, 0.1f);
            hh[j] = __float2half(o[j]);
        }
        *(float4*)&d_K[(size_t)(row0 + i) * Nn + col0]     = *(float4*)&o[0];
        *(float4*)&d_K[(size_t)(row0 + i) * Nn + col0 + 4] = *(float4*)&o[4];
        *(uint4*)&d_Kh[(size_t)(row0 + i) * Nn + col0]     = *(uint4*)hh;
    }
}

// ---------------- transpose: K -> KT (fp32) + KTh (fp16), one-time ----------
__global__ void transpose_kernel() {
    __shared__ float tile[32][33];
    int tx = threadIdx.x, ty = threadIdx.y;
    int xi = (blockIdx.x << 5) + tx;
    int yi = (blockIdx.y << 5) + ty;
#pragma unroll
    for (int j = 0; j < 32; j += 8)
        tile[ty + j][tx] = d_K[(size_t)(yi + j) * Nn + xi];
    __syncthreads();
    int xo = (blockIdx.y << 5) + tx;
    int yo = (blockIdx.x << 5) + ty;
#pragma unroll
    for (int j = 0; j < 32; j += 8) {
        float v = tile[tx][ty + j];
        d_KT [(size_t)(yo + j) * Nn + xo] = v;
        d_KTh[(size_t)(yo + j) * Nn + xo] = __float2half(v);
    }
}

// ====== LSE PASS: 4 rows/block INTERLEAVED fp16 screen ======================
// vin chunk loaded once per iteration and consumed by all 4 rows (amortizes
// the vector L2 traffic 4x). Per-row bit-path FROZEN (identical to R15/R16):
// sweep1 max -> ballot collect at thr_s=m_s-96 (fp16 superset proof) ->
// exact fp32 gather -> exact max -> parallel exp -> per-row FROZEN-order sums.
template <int DIR>
__global__ void __launch_bounds__(256) lse_pass_kernel() {
    __shared__ float wmax[8][RPB];
    __shared__ float bmax_s[RPB];
    __shared__ float m_sh[RPB];
    __shared__ int   okr[RPB];
    __shared__ int   seg_cnt[RPB][8];
    __shared__ short seg_list[RPB][8][SEGCAP];
    __shared__ float seg_val[RPB][8][SEGCAP];

    int t   = threadIdx.x;
    int lane = t & 31, wid = t >> 5;
    int row0 = blockIdx.x * RPB;
    const __half* __restrict__ Hbase = (DIR == 0) ? d_Kh : d_KTh;
    const float*  __restrict__ Mbase = (DIR == 0) ? d_K  : d_KT;
    const float*  __restrict__ vin   = (DIR == 0) ? d_beta : d_alpha;

    int segbase = wid << 10;             // 1024 elems per warp segment

    const __half* H0 = Hbase + (size_t)(row0 + 0) * Nn;
    const __half* H1 = Hbase + (size_t)(row0 + 1) * Nn;
    const __half* H2 = Hbase + (size_t)(row0 + 2) * Nn;
    const __half* H3 = Hbase + (size_t)(row0 + 3) * Nn;

    // ---- sweep 1: 4-row interleaved max ----
    float lm[RPB];
#pragma unroll
    for (int r = 0; r < RPB; r++) lm[r] = __int_as_float(0xff800000);

    for (int r2 = 0; r2 < 4; r2++) {
        int i0 = segbase + (r2 << 8) + (lane << 3);
        float4 b0 = *(const float4*)(vin + i0);
        float4 b1 = *(const float4*)(vin + i0 + 4);
        uint4 hv[RPB];
        hv[0] = *(const uint4*)(H0 + i0);
        hv[1] = *(const uint4*)(H1 + i0);
        hv[2] = *(const uint4*)(H2 + i0);
        hv[3] = *(const uint4*)(H3 + i0);
#pragma unroll
        for (int r = 0; r < RPB; r++) {
            __half2* hp = (__half2*)&hv[r];
            float2 f0 = __half22float2(hp[0]);
            float2 f1 = __half22float2(hp[1]);
            float2 f2 = __half22float2(hp[2]);
            float2 f3 = __half22float2(hp[3]);
            float z0 = __fadd_rn(f0.x, b0.x), z1 = __fadd_rn(f0.y, b0.y);
            float z2 = __fadd_rn(f1.x, b0.z), z3 = __fadd_rn(f1.y, b0.w);
            float z4 = __fadd_rn(f2.x, b1.x), z5 = __fadd_rn(f2.y, b1.y);
            float z6 = __fadd_rn(f3.x, b1.z), z7 = __fadd_rn(f3.y, b1.w);
            lm[r] = fmaxf(lm[r], fmaxf(fmaxf(z0, z1), fmaxf(z2, z3)));
            lm[r] = fmaxf(lm[r], fmaxf(fmaxf(z4, z5), fmaxf(z6, z7)));
        }
    }
#pragma unroll
    for (int r = 0; r < RPB; r++) {
#pragma unroll
        for (int off = 16; off; off >>= 1)
            lm[r] = fmaxf(lm[r], __shfl_down_sync(0xffffffffu, lm[r], off));
    }
    if (lane == 0) {
#pragma unroll
        for (int r = 0; r < RPB; r++) { wmax[wid][r] = lm[r]; seg_cnt[r][wid] = 0; }
    }
    __syncthreads();
    if (t < RPB) {
        float m = wmax[0][t];
#pragma unroll
        for (int w = 1; w < 8; w++) m = fmaxf(m, wmax[w][t]);
        bmax_s[t] = m;
    }
    __syncthreads();
    float thr_s[RPB];
#pragma unroll
    for (int r = 0; r < RPB; r++) thr_s[r] = bmax_s[r] - 96.0f;

    // ---- sweep 2 (L1-hot): interleaved mask + ascending emission ----
    {
        int cnt[RPB];
#pragma unroll
        for (int r = 0; r < RPB; r++) cnt[r] = 0;

        for (int r2 = 0; r2 < 4; r2++) {
            int i0 = segbase + (r2 << 8) + (lane << 3);
            float4 b0 = *(const float4*)(vin + i0);
            float4 b1 = *(const float4*)(vin + i0 + 4);
            uint4 hv[RPB];
            hv[0] = *(const uint4*)(H0 + i0);
            hv[1] = *(const uint4*)(H1 + i0);
            hv[2] = *(const uint4*)(H2 + i0);
            hv[3] = *(const uint4*)(H3 + i0);
            unsigned m8[RPB];
#pragma unroll
            for (int r = 0; r < RPB; r++) {
                __half2* hp = (__half2*)&hv[r];
                float2 f0 = __half22float2(hp[0]);
                float2 f1 = __half22float2(hp[1]);
                float2 f2 = __half22float2(hp[2]);
                float2 f3 = __half22float2(hp[3]);
                unsigned mm = 0;
                mm |= (__fadd_rn(f0.x, b0.x) >= thr_s[r]) ? 1u   : 0u;
                mm |= (__fadd_rn(f0.y, b0.y) >= thr_s[r]) ? 2u   : 0u;
                mm |= (__fadd_rn(f1.x, b0.z) >= thr_s[r]) ? 4u   : 0u;
                mm |= (__fadd_rn(f1.y, b0.w) >= thr_s[r]) ? 8u   : 0u;
                mm |= (__fadd_rn(f2.x, b1.x) >= thr_s[r]) ? 16u  : 0u;
                mm |= (__fadd_rn(f2.y, b1.y) >= thr_s[r]) ? 32u  : 0u;
                mm |= (__fadd_rn(f3.x, b1.z) >= thr_s[r]) ? 64u  : 0u;
                mm |= (__fadd_rn(f3.y, b1.w) >= thr_s[r]) ? 128u : 0u;
                m8[r] = mm;
            }
#pragma unroll
            for (int r = 0; r < RPB; r++) {
                unsigned act = __ballot_sync(0xffffffffu, m8[r] != 0);
                while (act) {                  // uniform across warp
                    int la = __ffs(act) - 1;
                    unsigned mm = __shfl_sync(0xffffffffu, m8[r], la);
                    if (lane == 0) {
                        int base = (r2 << 8) + (la << 3);
                        while (mm) {
                            int b = __ffs(mm) - 1;
                            if (cnt[r] < SEGCAP) seg_list[r][wid][cnt[r]] = (short)(base + b);
                            cnt[r]++;
                            mm &= mm - 1;
                        }
                    }
                    act &= act - 1;
                }
            }
        }
        if (lane == 0) {
#pragma unroll
            for (int r = 0; r < RPB; r++) seg_cnt[r][wid] = cnt[r];
        }
        __syncwarp();
        // warp-parallel gather of EXACT fp32 z for all 4 rows
#pragma unroll
        for (int r = 0; r < RPB; r++) {
            const float* Mx = Mbase + (size_t)(row0 + r) * Nn;
            int cc = seg_cnt[r][wid]; if (cc > SEGCAP) cc = SEGCAP;
            for (int p = lane; p < cc; p += 32) {
                int idx = segbase + seg_list[r][wid][p];
                seg_val[r][wid][p] = __fadd_rn(Mx[idx], vin[idx]);
            }
        }
    }
    __syncthreads();

    // per-row ok + exact max (threads 0..3, one row each)
    if (t < RPB) {
        bool ok = true;
#pragma unroll
        for (int w = 0; w < 8; w++) ok &= (seg_cnt[t][w] <= SEGCAP);
        okr[t] = ok;
        if (ok) {
            float m = __int_as_float(0xff800000);
            for (int w = 0; w < 8; w++) {
                int cnt = seg_cnt[t][w];
                for (int p = 0; p < cnt; p++) m = fmaxf(m, seg_val[t][w][p]);
            }
            m_sh[t] = m;
        }
    }
    __syncthreads();

    // parallel exp: warp pair (2r, 2r+1) handles row r, 4 segments each
    {
        int r = wid >> 1;
        if (okr[r]) {
            float m = m_sh[r];
            float thr = m - 70.0f;
            int s0 = (wid & 1) * 4;
#pragma unroll
            for (int s = 0; s < 4; s++) {
                int cnt = seg_cnt[r][s0 + s];
                for (int p = lane; p < cnt; p += 32) {
                    float zv = seg_val[r][s0 + s][p];
                    seg_val[r][s0 + s][p] = (zv >= thr) ? exp_fma(__fadd_rn(zv, -m)) : -1.0f;
                }
            }
        }
    }
    __syncthreads();

    // frozen-order additions, one thread per row
    if (t < RPB) {
        int row = row0 + t;
        if (okr[t]) {
            float m = m_sh[t];
            float S;
            if (DIR == 0) {
                float s[8];
#pragma unroll
                for (int i = 0; i < 8; i++) s[i] = 0.0f;
                for (int w = 0; w < 8; w++) {
                    int base = w << 10, cnt = seg_cnt[t][w];
                    for (int p = 0; p < cnt; p++) {
                        float e = seg_val[t][w][p];
                        if (e >= 0.0f) {
                            int idx = base + seg_list[t][w][p];
                            s[idx & 7] = __fadd_rn(s[idx & 7], e);
                        }
                    }
                }
                float w0 = __fadd_rn(s[0], s[4]);
                float w1 = __fadd_rn(s[1], s[5]);
                float w2 = __fadd_rn(s[2], s[6]);
                float w3 = __fadd_rn(s[3], s[7]);
                S = __fadd_rn(__fadd_rn(w0, w2), __fadd_rn(w1, w3));
            } else {
                float acc = 0.0f;
                for (int w = 0; w < 8; w++) {
                    int cnt = seg_cnt[t][w];
                    for (int p = 0; p < cnt; p++) {
                        float e = seg_val[t][w][p];
                        if (e >= 0.0f) acc = __fadd_rn(acc, e);
                    }
                }
                S = acc;
            }
            float res = -__fadd_rn(log_fma(S), m);
            if (DIR == 0) d_alpha[row] = res; else d_beta[row] = res;
        } else {
            // exact in-order fallback over full fp32 row (never expected)
            const float* Mx = Mbase + (size_t)row * Nn;
            float m = __int_as_float(0xff800000);
            for (int q = 0; q < Nn; q++)
                m = fmaxf(m, __fadd_rn(Mx[q], vin[q]));
            float thr = m - 70.0f;
            float S;
            if (DIR == 0) {
                float s[8];
#pragma unroll
                for (int i = 0; i < 8; i++) s[i] = 0.0f;
                for (int q = 0; q < Nn; q++) {
                    float zv = __fadd_rn(Mx[q], vin[q]);
                    if (zv >= thr)
                        s[q & 7] = __fadd_rn(s[q & 7], exp_fma(__fadd_rn(zv, -m)));
                }
                float w0 = __fadd_rn(s[0], s[4]);
                float w1 = __fadd_rn(s[1], s[5]);
                float w2 = __fadd_rn(s[2], s[6]);
                float w3 = __fadd_rn(s[3], s[7]);
                S = __fadd_rn(__fadd_rn(w0, w2), __fadd_rn(w1, w3));
            } else {
                float acc = 0.0f;
                for (int q = 0; q < Nn; q++) {
                    float zv = __fadd_rn(Mx[q], vin[q]);
                    if (zv >= thr)
                        acc = __fadd_rn(acc, exp_fma(__fadd_rn(zv, -m)));
                }
                S = acc;
            }
            float res = -__fadd_rn(log_fma(S), m);
            if (DIR == 0) d_alpha[row] = res; else d_beta[row] = res;
        }
    }
}

// ---------------- argmax over P = exp_fma(fl(fl(K+alpha)+beta)) (FROZEN) ----
__global__ void __launch_bounds__(256) argmax_kernel() {
    int rowbase = blockIdx.x << 3;
    int t = threadIdx.x;
    float a[8];
#pragma unroll
    for (int r = 0; r < 8; r++) a[r] = d_alpha[rowbase + r];

    float bv[8]; int bi_[8];
#pragma unroll
    for (int r = 0; r < 8; r++) { bv[r] = -1.0f; bi_[r] = Nn; }

    for (int c = t << 2; c < Nn; c += 1024) {
        float4 betav = *(const float4*)(d_beta + c);
#pragma unroll
        for (int r = 0; r < 8; r++) {
            float4 v = *(const float4*)(d_K + (size_t)(rowbase + r) * Nn + c);
            float w;
            w = exp_fma(__fadd_rn(__fadd_rn(v.x, a[r]), betav.x)); if (w > bv[r]) { bv[r] = w; bi_[r] = c; }
            w = exp_fma(__fadd_rn(__fadd_rn(v.y, a[r]), betav.y)); if (w > bv[r]) { bv[r] = w; bi_[r] = c + 1; }
            w = exp_fma(__fadd_rn(__fadd_rn(v.z, a[r]), betav.z)); if (w > bv[r]) { bv[r] = w; bi_[r] = c + 2; }
            w = exp_fma(__fadd_rn(__fadd_rn(v.w, a[r]), betav.w)); if (w > bv[r]) { bv[r] = w; bi_[r] = c + 3; }
        }
    }
#pragma unroll
    for (int r = 0; r < 8; r++) {
#pragma unroll
        for (int off = 16; off; off >>= 1) {
            float ov = __shfl_down_sync(0xffffffffu, bv[r], off);
            int   oi = __shfl_down_sync(0xffffffffu, bi_[r], off);
            if (ov > bv[r] || (ov == bv[r] && oi < bi_[r])) { bv[r] = ov; bi_[r] = oi; }
        }
    }
    __shared__ float svv[8][8];
    __shared__ int   sii[8][8];
    int wid = t >> 5, lane = t & 31;
    if (lane == 0) {
#pragma unroll
        for (int r = 0; r < 8; r++) { svv[r][wid] = bv[r]; sii[r][wid] = bi_[r]; }
    }
    __syncthreads();
    if (t < 8) {
        float V = -1.0f; int I = Nn;
#pragma unroll
        for (int w = 0; w < 8; w++) {
            float ov = svv[t][w]; int oi = sii[t][w];
            if (ov > V || (ov == V && oi < I)) { V = ov; I = oi; }
        }
        d_idx[rowbase + t] = I;
    }
}

// ---------------- out = concat(x0, x1[idx]) ----------------
__global__ void output_kernel(const float* __restrict__ x0,
                              const float* __restrict__ x1,
                              float* __restrict__ out) {
    int row = blockIdx.x;
    int t   = threadIdx.x;
    const float4* s0 = (const float4*)(x0 + (size_t)row * Dd);
    ((float4*)(out + (size_t)row * Dd))[t] = s0[t];
    int j = d_idx[row];
    const float4* s1 = (const float4*)(x1 + (size_t)j * Dd);
    ((float4*)(out + (size_t)Nn * Dd + (size_t)row * Dd))[t] = s1[t];
}

// ---------------- launch ----------------
extern "C" void kernel_launch(void* const* d_in, const int* in_sizes, int n_in,
                              void* d_out, int out_size) {
    const float* x0 = (const float*)d_in[0];
    const float* x1 = (const float*)d_in[1];
    float* out = (float*)d_out;

    init_kernel<<<8, 1024>>>();
    rowsq_kernel<<<2 * (Nn / 256), 256>>>(x0, x1);

    dim3 gg(Nn / 128, Nn / 128);
    gemm_kernel<<<gg, 256>>>(x0, x1);

    dim3 tg(Nn / 32, Nn / 32), tb(32, 8);
    transpose_kernel<<<tg, tb>>>();

    for (int it = 0; it < 100; it++) {
        lse_pass_kernel<0><<<Nn / RPB, 256>>>();
        lse_pass_kernel<1><<<Nn / RPB, 256>>>();
    }

    argmax_kernel<<<Nn / 8, 256>>>();
    output_kernel<<<Nn, 128>>>(x0, x1, out);
}